// round 5
// baseline (speedup 1.0000x reference)
#include <cuda_runtime.h>
#include <cstdint>

#define NROWS 32768
#define DDIM  128
#define KCB   1024
#define MLVL  4
#define NDTOT (NROWS*DDIM)

// argmin-GEMM tiling
#define TR 128      // rows per CTA
#define TK 64       // k per tile
#define DC 32       // d chunk
#define CBPAD 36    // DC + 4 pad (2-way max conflict on cb reads)
#define NSTAGE ((KCB/TK)*(DDIM/DC))   // 64 load stages

static const int SMEM_FLOATS = TR*DDIM + 2*TK*CBPAD + KCB;  // res + 2x cb buf + e2
static const int SMEM_BYTES  = SMEM_FLOATS * 4;             // 88,064 B dynamic

// scratch (allocation-free contract: __device__ globals)
__device__ float  g_res[NDTOT];
__device__ float  g_qsum[NDTOT];
__device__ float  g_r2[NROWS];
__device__ float  g_e2[MLVL*KCB];
__device__ double g_loss;

// ---------------------------------------------------------------------------
// e2[l][k] = fl32 of sum_d fl32(cb*cb) -- squared in fp32 (matches reference
// elementwise cb*cb), accumulated in double -> canonical single rounding.
// ---------------------------------------------------------------------------
__global__ void e2_kernel(const float* __restrict__ cb) {
    int gw   = (blockIdx.x * blockDim.x + threadIdx.x) >> 5;
    int lane = threadIdx.x & 31;
    if (gw >= MLVL*KCB) return;
    const float* row = cb + (size_t)gw * DDIM;
    double s = 0.0;
    #pragma unroll
    for (int i = 0; i < 4; i++) {
        float v  = row[lane + 32*i];
        float sq = v * v;           // fp32 square like reference
        s += (double)sq;
    }
    #pragma unroll
    for (int off = 16; off; off >>= 1)
        s += __shfl_xor_sync(0xffffffffu, s, off);
    if (lane == 0) g_e2[gw] = (float)s;
}

// ---------------------------------------------------------------------------
// init: residual = x, q_sum = 0, r2[row] = sum(x^2). r2 accumulation order is
// argmin-irrelevant: r2 is a grid multiple near 128, so fl(r2+e2_k) = r2 +
// grid-round(e2_k) and any r2 delta shifts all dist_k uniformly (same binade).
// ---------------------------------------------------------------------------
__global__ void init_kernel(const float* __restrict__ x) {
    int row = blockIdx.x, t = threadIdx.x;
    size_t off = (size_t)row * DDIM + t;
    float v = x[off];
    g_res[off]  = v;
    g_qsum[off] = 0.0f;
    __shared__ float red[DDIM];
    red[t] = v * v;
    __syncthreads();
    #pragma unroll
    for (int s = 64; s > 0; s >>= 1) {
        if (t < s) red[t] += red[t + s];
        __syncthreads();
    }
    if (t == 0) {
        g_r2[row] = red[0];
        if (row == 0) g_loss = 0.0;
    }
}

// ---------------------------------------------------------------------------
// Fused argmin-GEMM + update. CTA: TR=128 rows x full K=1024. 256 threads =
// (tx:16, ty:16); micro-tile 8 rows x 4 k (k strided by 16). Residual tile
// resident in smem; codebook double-buffered in 64k x 32d stages (one sync
// per stage; each stage = 512 float4 -> every thread loads slots {tid,tid+256}).
// dist_k = RN( fl(r2 + e2_k) - 2*dot_k )  -- identical rounding chain to
// jax's (r2 + e2) - 2*mm (2*dot exact inside the fma).
// First-min tiebreak: ascending k within thread, index tiebreak in reduce.
// Epilogue (fused former update_kernel): broadcast winning indices via smem,
// gather q = cb[idx], update g_res / g_qsum, emit next-level r2, one double
// loss atomic per CTA. Each CTA touches only its own rows -> race-free.
// ---------------------------------------------------------------------------
__global__ void __launch_bounds__(256, 2)
argmin_fused_kernel(const float* __restrict__ cb, int lvl) {
    extern __shared__ float sm[];
    float* sres = sm;                        // [TR][DDIM]
    float* scb  = sm + TR*DDIM;              // [2][TK][CBPAD]
    float* se2  = scb + 2*TK*CBPAD;          // [KCB]
    __shared__ int   sidx[TR];
    __shared__ float lred[TR/2 + TR];        // row loss partials + padding slack

    const int tid = threadIdx.x;
    const int tx  = tid & 15;
    const int ty  = tid >> 4;
    const int r0  = blockIdx.x * TR;

    // this thread's two cb-load slots (covers all 512 float4 of a stage)
    const int ldk0 = tid >> 3;        // [0,32)
    const int ldc0 = tid & 7;         // [0,8)
    const int ldk1 = 32 + ldk0;       // [32,64)

    // stage e2 slice for this level
    for (int i = tid; i < KCB; i += 256) se2[i] = g_e2[lvl*KCB + i];

    // stage residual tile (coalesced float4, conflict-free STS)
    for (int i = tid; i < TR*DDIM/4; i += 256) {
        int row = i >> 5, c = i & 31;
        *(float4*)&sres[row*DDIM + 4*c] =
            *(const float4*)&g_res[(size_t)(r0 + row)*DDIM + 4*c];
    }

    // preload cb stage 0 (kt=0, dchunk=0) into buffer 0 -- both slots
    *(float4*)&scb[ldk0*CBPAD + 4*ldc0] =
        *(const float4*)&cb[(size_t)ldk0*DDIM + 4*ldc0];
    *(float4*)&scb[ldk1*CBPAD + 4*ldc0] =
        *(const float4*)&cb[(size_t)ldk1*DDIM + 4*ldc0];
    __syncthreads();

    float r2v[8];
    float bestD[8];
    int   bestI[8];
    #pragma unroll
    for (int i = 0; i < 8; i++) {
        r2v[i]   = g_r2[r0 + ty*8 + i];
        bestD[i] = __int_as_float(0x7f800000);  // +inf
        bestI[i] = 0;
    }

    for (int kt = 0; kt < KCB/TK; kt++) {
        float acc[8][4];
        #pragma unroll
        for (int i = 0; i < 8; i++)
            #pragma unroll
            for (int j = 0; j < 4; j++) acc[i][j] = 0.0f;

        #pragma unroll
        for (int dchunk = 0; dchunk < DDIM/DC; dchunk++) {
            const int st = kt*(DDIM/DC) + dchunk;
            float* cbuf = scb + (st & 1) * TK*CBPAD;

            // issue next-stage load into the other buffer (overlaps compute);
            // readers of that buffer synced at the end of stage st-1.
            if (st + 1 < NSTAGE) {
                int kt2 = (st + 1) >> 2, dc2 = (st + 1) & 3;
                float* nbuf = scb + ((st + 1) & 1) * TK*CBPAD;
                const float* src = cb + (size_t)(kt2*TK)*DDIM + dc2*DC;
                *(float4*)&nbuf[ldk0*CBPAD + 4*ldc0] =
                    *(const float4*)&src[(size_t)ldk0*DDIM + 4*ldc0];
                *(float4*)&nbuf[ldk1*CBPAD + 4*ldc0] =
                    *(const float4*)&src[(size_t)ldk1*DDIM + 4*ldc0];
            }

            #pragma unroll
            for (int dg = 0; dg < DC/4; dg++) {
                float4 cv[4];
                #pragma unroll
                for (int j = 0; j < 4; j++)
                    cv[j] = *(const float4*)&cbuf[(tx + 16*j)*CBPAD + dg*4];
                #pragma unroll
                for (int i = 0; i < 8; i++) {
                    float4 rv = *(const float4*)
                        &sres[(ty*8 + i)*DDIM + dchunk*DC + dg*4];
                    #pragma unroll
                    for (int j = 0; j < 4; j++) {
                        acc[i][j] = fmaf(rv.x, cv[j].x, acc[i][j]);
                        acc[i][j] = fmaf(rv.y, cv[j].y, acc[i][j]);
                        acc[i][j] = fmaf(rv.z, cv[j].z, acc[i][j]);
                        acc[i][j] = fmaf(rv.w, cv[j].w, acc[i][j]);
                    }
                }
            }
            __syncthreads();   // guards next-stage STS vs its readers
        }

        // epilogue: quantized distance + running first-min (k ascending in j)
        #pragma unroll
        for (int i = 0; i < 8; i++) {
            #pragma unroll
            for (int j = 0; j < 4; j++) {
                int kg = kt*TK + tx + 16*j;
                float r2pe2 = __fadd_rn(r2v[i], se2[kg]);
                float d2    = __fmaf_rn(-2.0f, acc[i][j], r2pe2);
                if (d2 < bestD[i]) { bestD[i] = d2; bestI[i] = kg; }
            }
        }
    }

    // reduce across the 16 tx lanes (xor<16 stays inside each 16-lane half).
    // Tiebreak: lowest index (matches jnp.argmin first-min).
    #pragma unroll
    for (int i = 0; i < 8; i++) {
        float d  = bestD[i];
        int   bi = bestI[i];
        #pragma unroll
        for (int off = 8; off; off >>= 1) {
            float od = __shfl_xor_sync(0xffffffffu, d,  off);
            int   oi = __shfl_xor_sync(0xffffffffu, bi, off);
            if (od < d || (od == d && oi < bi)) { d = od; bi = oi; }
        }
        if (tx == 0) sidx[ty*8 + i] = bi;
    }
    __syncthreads();

    // -------- fused update: 2 threads per row, 64 d each --------
    {
        const int urow  = tid >> 1;       // [0,128)
        const int uhalf = tid & 1;        // 0/1
        const int id    = sidx[urow];
        const float* qrow = cb + (size_t)id*DDIM + uhalf*64;
        float* gres = g_res  + (size_t)(r0 + urow)*DDIM + uhalf*64;
        float* gqs  = g_qsum + (size_t)(r0 + urow)*DDIM + uhalf*64;
        const float* srow = sres + urow*DDIM + uhalf*64;

        float part = 0.0f;
        #pragma unroll
        for (int i = 0; i < 16; i++) {
            float4 q  = *(const float4*)&qrow[4*i];
            float4 r  = *(const float4*)&srow[4*i];
            float4 rn;
            rn.x = __fadd_rn(r.x, -q.x);
            rn.y = __fadd_rn(r.y, -q.y);
            rn.z = __fadd_rn(r.z, -q.z);
            rn.w = __fadd_rn(r.w, -q.w);
            *(float4*)&gres[4*i] = rn;
            float4 qs = *(const float4*)&gqs[4*i];
            qs.x = __fadd_rn(qs.x, q.x);
            qs.y = __fadd_rn(qs.y, q.y);
            qs.z = __fadd_rn(qs.z, q.z);
            qs.w = __fadd_rn(qs.w, q.w);
            *(float4*)&gqs[4*i] = qs;
            part += rn.x*rn.x + rn.y*rn.y + rn.z*rn.z + rn.w*rn.w;
        }
        // combine the two halves of the row (adjacent lanes)
        part += __shfl_xor_sync(0xffffffffu, part, 1);
        if (uhalf == 0) {
            g_r2[r0 + urow] = part;       // next level's r2
            lred[urow] = part;            // loss partial
        }
    }
    __syncthreads();
    #pragma unroll
    for (int s = 64; s > 0; s >>= 1) {
        if (tid < s) lred[tid] += lred[tid + s];
        __syncthreads();
    }
    if (tid == 0) atomicAdd(&g_loss, (double)lred[0]);
}

// ---------------------------------------------------------------------------
// finalize: y = fl(x + fl(q_sum - x))  (straight-through forward, matching
// the reference bit pattern), loss = 1.25 * g_loss / (N*D) appended after y.
// ---------------------------------------------------------------------------
__global__ void finalize_kernel(const float* __restrict__ x,
                                float* __restrict__ out, int out_size) {
    int i = blockIdx.x * blockDim.x + threadIdx.x;
    if (i < NDTOT) {
        if (i < out_size) {
            float xf = x[i];
            float d  = __fadd_rn(g_qsum[i], -xf);
            out[i]   = __fadd_rn(xf, d);
        }
    } else if (i < out_size) {
        out[i] = (i == NDTOT) ? (float)(1.25 * g_loss / (double)NDTOT) : 0.0f;
    }
}

// ---------------------------------------------------------------------------
extern "C" void kernel_launch(void* const* d_in, const int* in_sizes, int n_in,
                              void* d_out, int out_size) {
    const float* x  = (const float*)d_in[0];   // [8,4096,128] fp32
    const float* cb = (const float*)d_in[1];   // [4,1024,128] fp32
    float* out = (float*)d_out;

    cudaFuncSetAttribute(argmin_fused_kernel,
                         cudaFuncAttributeMaxDynamicSharedMemorySize, SMEM_BYTES);

    e2_kernel<<<(MLVL*KCB*32 + 255)/256, 256>>>(cb);
    init_kernel<<<NROWS, DDIM>>>(x);

    for (int l = 0; l < MLVL; l++) {
        const float* cbl = cb + (size_t)l * KCB * DDIM;
        argmin_fused_kernel<<<NROWS/TR, 256, SMEM_BYTES>>>(cbl, l);
    }

    int total = out_size > NDTOT ? out_size : NDTOT;
    finalize_kernel<<<(total + 255)/256, 256>>>(x, out, out_size);
}